// round 11
// baseline (speedup 1.0000x reference)
#include <cuda_runtime.h>
#include <cuda_bf16.h>
#include <math.h>

#define INF_F 1e10f
#define L2E   1.4426950408889634f
#define LN2   0.6931471805599453f
#define NDIAG 2072ull
#define SENT_U 0x7FC00000u

// ---------------- scratch (device globals) -------------------------------------
__device__ float g_norm[3u * 8192u * 64u];               // normalized rows
__device__ float g_cost[32ull * NDIAG * 1024ull];        // diag-major cost*L2E, PAD=8 lead
__device__ float g_hrow[32][16][1024];                   // bottom row of 64-row strip q
__device__ float g_R[32];                                // DTW results (log2-scaled)

__device__ __forceinline__ float fexp2(float x) {
    float y; asm("ex2.approx.f32 %0, %1;" : "=f"(y) : "f"(x)); return y;
}
__device__ __forceinline__ float flog2(float x) {
    float y; asm("lg2.approx.f32 %0, %1;" : "=f"(y) : "f"(x)); return y;
}
__device__ __forceinline__ float ld_rlx(const float* p) {
    float v; asm volatile("ld.relaxed.gpu.global.f32 %0, [%1];" : "=f"(v) : "l"(p)); return v;
}
__device__ __forceinline__ void st_rlx(float* p, float v) {
    asm volatile("st.relaxed.gpu.global.f32 [%0], %1;" :: "l"(p), "f"(v) : "memory");
}
typedef unsigned long long u64;
__device__ __forceinline__ u64 ffma2(u64 a, u64 b, u64 c) {
    u64 d; asm("fma.rn.f32x2 %0, %1, %2, %3;" : "=l"(d) : "l"(a), "l"(b), "l"(c)); return d;
}
__device__ __forceinline__ u64 pack2(float x) {
    u64 d; asm("mov.b64 %0, {%1, %1};" : "=l"(d) : "f"(x)); return d;
}

// ---------------- kernel 0: fill halo buffer with sentinel -----------------------
__global__ void init_kernel() {
    unsigned t = blockIdx.x * 512u + threadIdx.x;        // 524,288 words
    ((unsigned*)g_hrow)[t] = SENT_U;
}

// ---------------- kernel 1: row-wise L2 normalize -------------------------------
__global__ void norm_kernel(const float* __restrict__ A,
                            const float* __restrict__ B,
                            const float* __restrict__ C) {
    const int sel  = blockIdx.y;
    const int lane = threadIdx.x & 31;
    const int row  = blockIdx.x * 8 + (threadIdx.x >> 5);
    const float* src = (sel == 0) ? A : ((sel == 1) ? B : C);

    float2 v = *(const float2*)(src + (size_t)row * 64 + lane * 2);
    float ss = v.x * v.x + v.y * v.y;
    #pragma unroll
    for (int o = 16; o > 0; o >>= 1) ss += __shfl_xor_sync(0xffffffffu, ss, o);
    float scale = 1.0f / fmaxf(sqrtf(ss), 1e-8f);
    float* dst = g_norm + (size_t)sel * (8192u * 64u) + (size_t)row * 64 + lane * 2;
    *(float2*)dst = make_float2(v.x * scale, v.y * scale);
}

// ---------------- kernel 2: cost = L2E*(1 - dot), DIAGONAL-major (PAD=8) --------
__global__ void __launch_bounds__(64) cost_kernel() {
    const int pb   = blockIdx.z;
    const int p    = pb >> 3;
    const int bat  = pb & 7;
    const int asel = p >> 1;                 // TGT(0)/OTH(1)
    const int bsel = (p & 1) ? asel : 2;     // self or X(2)

    const float* Abase = g_norm + ((size_t)asel * 8192u + (size_t)bat * 1024u) * 64u;
    const float* Bbase = g_norm + ((size_t)bsel * 8192u + (size_t)bat * 1024u) * 64u;
    const int i0 = blockIdx.x * 64;
    const int j0 = blockIdx.y * 64;

    __shared__ float sAT[64 * 64];
    __shared__ float sBT[64 * 64];
    const int tid = threadIdx.x;

    {
        const float4* ap = (const float4*)(Abase + (size_t)(i0 + tid) * 64);
        const float4* bp = (const float4*)(Bbase + (size_t)(j0 + tid) * 64);
        #pragma unroll
        for (int q = 0; q < 16; q++) {
            float4 va = ap[q];
            sAT[(4 * q + 0) * 64 + tid] = va.x;
            sAT[(4 * q + 1) * 64 + tid] = va.y;
            sAT[(4 * q + 2) * 64 + tid] = va.z;
            sAT[(4 * q + 3) * 64 + tid] = va.w;
            float4 vb = bp[q];
            sBT[(4 * q + 0) * 64 + tid] = vb.x;
            sBT[(4 * q + 1) * 64 + tid] = vb.y;
            sBT[(4 * q + 2) * 64 + tid] = vb.z;
            sBT[(4 * q + 3) * 64 + tid] = vb.w;
        }
    }
    __syncthreads();

    const int ti = tid >> 3;
    const int tj = tid & 7;

    u64 acc[8][4];
    #pragma unroll
    for (int r = 0; r < 8; r++)
        #pragma unroll
        for (int c = 0; c < 4; c++) acc[r][c] = 0ull;

    #pragma unroll
    for (int k = 0; k < 64; k++) {
        float4 t0 = *(const float4*)&sAT[k * 64 + ti * 8];
        float4 t1 = *(const float4*)&sAT[k * 64 + ti * 8 + 4];
        u64 a2[8];
        a2[0] = pack2(t0.x); a2[1] = pack2(t0.y); a2[2] = pack2(t0.z); a2[3] = pack2(t0.w);
        a2[4] = pack2(t1.x); a2[5] = pack2(t1.y); a2[6] = pack2(t1.z); a2[7] = pack2(t1.w);
        ulonglong2 u0 = *(const ulonglong2*)&sBT[k * 64 + tj * 8];
        ulonglong2 u1 = *(const ulonglong2*)&sBT[k * 64 + tj * 8 + 4];
        u64 b2[4] = {u0.x, u0.y, u1.x, u1.y};
        #pragma unroll
        for (int r = 0; r < 8; r++)
            #pragma unroll
            for (int c = 0; c < 4; c++)
                acc[r][c] = ffma2(a2[r], b2[c], acc[r][c]);
    }
    __syncthreads();

    float* Cs = sAT;   // restage (alias) with affine transform applied
    #pragma unroll
    for (int r = 0; r < 8; r++) {
        float v[8];
        #pragma unroll
        for (int c = 0; c < 4; c++) {
            float lo, hi;
            asm("mov.b64 {%0, %1}, %2;" : "=f"(lo), "=f"(hi) : "l"(acc[r][c]));
            v[2 * c]     = fmaf(lo, -L2E, L2E);
            v[2 * c + 1] = fmaf(hi, -L2E, L2E);
        }
        *(float4*)&Cs[(ti * 8 + r) * 64 + tj * 8]     = make_float4(v[0], v[1], v[2], v[3]);
        *(float4*)&Cs[(ti * 8 + r) * 64 + tj * 8 + 4] = make_float4(v[4], v[5], v[6], v[7]);
    }
    __syncthreads();

    float* out = g_cost + (size_t)pb * (NDIAG * 1024ull);
    const int kbase = i0 + j0 + 8;            // PAD=8 leading diagonals
    for (int d = 0; d < 127; d++) {
        int lo = d - 63; if (lo < 0) lo = 0;
        int hi = d;      if (hi > 63) hi = 63;
        int i = lo + tid;
        if (i <= hi)
            out[(size_t)(kbase + d) * 1024u + (i0 + i)] = Cs[i * 64 + (d - i)];
    }
}

// ---------------- kernel 3: soft-DTW, dual-chain 64-row strips -------------------
// warp (prob, q) owns rows r0=64q .. r0+63 as two skewed chains:
//   A: lane l = row r0+l,    step s computes col s-l        (s in [l, l+1023])
//   B: lane l = row r0+32+l, step s computes col s-33-l     (s in [l+33, l+1056])
// A<->B handoff in registers (shfl idx31 + 2-deep delay line). Cross-warp halo via
// sentinel protocol (15 hops). 136 groups x 8 = 1088 steps.
__global__ void __launch_bounds__(128) dp_kernel() {
    const int wslot = threadIdx.x >> 5;
    const int wid   = blockIdx.x * 4 + wslot;     // 0..511
    const int lane  = threadIdx.x & 31;
    const int prob  = wid >> 4;
    const int q     = wid & 15;
    const int r0    = q * 64;
    const bool has_up = (q > 0);

    const float* cbaseA = g_cost + ((size_t)prob * NDIAG + (unsigned)(r0 + 8)) * 1024ull
                        + r0 + lane;
    const float* cbaseB = g_cost + ((size_t)prob * NDIAG + (unsigned)(r0 + 7)) * 1024ull
                        + r0 + 32 + lane;
    const float* hin  = &g_hrow[prob][has_up ? (q - 1) : 0][0];
    float*       hout = &g_hrow[prob][q][0];
    const int    lid8 = lane & 7;

    // 16-deep cost register pipes
    float cA[16], cB[16];
    #pragma unroll
    for (int k = 0; k < 16; k++) {
        cA[k] = __ldg(cbaseA + (size_t)k * 1024u);
        cB[k] = __ldg(cbaseB + (size_t)k * 1024u);
    }

    float rA = INF_F, upA = INF_F, dgA = (q == 0 && lane == 0) ? 0.0f : INF_F;
    float rB = INF_F, upB = INF_F, dgB = INF_F;
    float h1 = INF_F, h2 = INF_F;   // delay line: h2 = A.lane31 r_cur from 2 steps ago

    // 3-slot halo pipeline (cross-warp input for chain A)
    float hv0 = INF_F, hv1 = 0.0f, hv2 = 0.0f;
    if (has_up) {
        hv0 = ld_rlx(hin + lid8);
        while (__any_sync(0xffffffffu, __float_as_uint(hv0) == SENT_U)) {
            __nanosleep(128);
            hv0 = ld_rlx(hin + lid8);
        }
        hv1 = ld_rlx(hin + 8 + lid8);
        hv2 = ld_rlx(hin + 16 + lid8);
    }

    // group-advanced pointers
    const float* cpfA = cbaseA + 16 * 1024;
    const float* cpfB = cbaseB + 16 * 1024;
    float*       hpB  = hout - 64;           // store for step s0+k is hpB[k] (col s-64)

#define STEP_A(SLOT0, KK, SS, MA)                                              \
    {                                                                          \
        float Dv = cA[(SLOT0) + (KK)];                                         \
        cA[(SLOT0) + (KK)] = __ldg(cpfA + (KK) * 1024);                        \
        float topv = __shfl_sync(0xffffffffu, hv0, (KK));                      \
        float u = (lane == 0) ? topv : upA;                                    \
        float p   = fminf(u, dgA);                                             \
        float qq  = fmaxf(u, dgA);                                             \
        float mn  = fminf(p, rA);                                              \
        float mx  = fmaxf(qq, rA);                                             \
        float mid = fmaxf(p, fminf(qq, rA));                                   \
        float curv = (Dv + mn) - flog2((1.0f + fexp2(mn - mid)) + fexp2(mn - mx)); \
        bool act = (MA == 0) ? true                                            \
                 : ((MA == 1) ? ((SS) >= lane) : (((SS) - lane) <= 1023));     \
        rA  = act ? curv : rA;                                                 \
        dgA = u;                                                               \
        upA = __shfl_up_sync(0xffffffffu, rA, 1);                              \
    }

#define STEP_B(SLOT0, KK, SS, MB)                                              \
    {                                                                          \
        float Dv = cB[(SLOT0) + (KK)];                                         \
        cB[(SLOT0) + (KK)] = __ldg(cpfB + (KK) * 1024);                        \
        float u = (lane == 0) ? h2 : upB;                                      \
        float p   = fminf(u, dgB);                                             \
        float qq  = fmaxf(u, dgB);                                             \
        float mn  = fminf(p, rB);                                              \
        float mx  = fmaxf(qq, rB);                                             \
        float mid = fmaxf(p, fminf(qq, rB));                                   \
        float curv = (Dv + mn) - flog2((1.0f + fexp2(mn - mid)) + fexp2(mn - mx)); \
        bool act = (MB == 0) ? true                                            \
                 : ((MB == 1) ? ((SS) >= lane + 33) : ((SS) <= lane + 1056));  \
        rB  = act ? curv : rB;                                                 \
        if (lane == 31 && act) st_rlx(hpB + (KK), rB);                         \
        dgB = u;                                                               \
        upB = __shfl_up_sync(0xffffffffu, rB, 1);                              \
        h2  = h1;                                                              \
        h1  = __shfl_sync(0xffffffffu, rA, 31);                                \
    }

#define HSHIFT()                                                               \
    { h2 = h1; h1 = __shfl_sync(0xffffffffu, rA, 31); }

#define PRE_B(SLOT0, KK)                                                       \
    { cB[(SLOT0) + (KK)] = __ldg(cpfB + (KK) * 1024); }

#define ADV() { cpfA += 8 * 1024; cpfB += 8 * 1024; hpB += 8; }

#define ROT(G)                                                                 \
    if (has_up && (G) <= 126) {                                                \
        while (__any_sync(0xffffffffu, __float_as_uint(hv1) == SENT_U))        \
            hv1 = ld_rlx(hin + 8 * ((G) + 1) + lid8);                          \
        hv0 = hv1; hv1 = hv2;                                                  \
        int a = 8 * ((G) + 3); if (a > 1016) a = 1016;                         \
        hv2 = ld_rlx(hin + a + lid8);                                          \
    }

    // ---- groups 0..3 (s = 0..31): A prologue, B inactive (prefetch only) ----
    {
        #pragma unroll
        for (int kk = 0; kk < 8; kk++) { STEP_A(0, kk, kk, 1)       PRE_B(0, kk) HSHIFT() }
        ROT(0) ADV()
        #pragma unroll
        for (int kk = 0; kk < 8; kk++) { STEP_A(8, kk, 8 + kk, 1)   PRE_B(8, kk) HSHIFT() }
        ROT(1) ADV()
        #pragma unroll
        for (int kk = 0; kk < 8; kk++) { STEP_A(0, kk, 16 + kk, 1)  PRE_B(0, kk) HSHIFT() }
        ROT(2) ADV()
        #pragma unroll
        for (int kk = 0; kk < 8; kk++) { STEP_A(8, kk, 24 + kk, 1)  PRE_B(8, kk) HSHIFT() }
        ROT(3) ADV()
    }

    // ---- groups 4..7 (s = 32..63): A lean, B prologue ----
    {
        #pragma unroll
        for (int kk = 0; kk < 8; kk++) { STEP_A(0, kk, 0, 0) STEP_B(0, kk, 32 + kk, 1) }
        ROT(4) ADV()
        #pragma unroll
        for (int kk = 0; kk < 8; kk++) { STEP_A(8, kk, 0, 0) STEP_B(8, kk, 40 + kk, 1) }
        ROT(5) ADV()
        #pragma unroll
        for (int kk = 0; kk < 8; kk++) { STEP_A(0, kk, 0, 0) STEP_B(0, kk, 48 + kk, 1) }
        ROT(6) ADV()
        #pragma unroll
        for (int kk = 0; kk < 8; kk++) { STEP_A(8, kk, 0, 0) STEP_B(8, kk, 56 + kk, 1) }
        ROT(7) ADV()
    }

    // ---- steady region: groups 8..127 (s = 64..1023), both lean ----
    for (int g = 8; g < 128; g += 2) {
        #pragma unroll
        for (int kk = 0; kk < 8; kk++) { STEP_A(0, kk, 0, 0) STEP_B(0, kk, 0, 0) }
        ROT(g) ADV()
        #pragma unroll
        for (int kk = 0; kk < 8; kk++) { STEP_A(8, kk, 0, 0) STEP_B(8, kk, 0, 0) }
        ROT(g + 1) ADV()
    }

    // ---- epilogue: groups 128..135 (s = 1024..1087), both masked ----
    #pragma unroll
    for (int gg = 0; gg < 4; gg++) {
        const int s0a = 1024 + 16 * gg;
        #pragma unroll
        for (int kk = 0; kk < 8; kk++) { STEP_A(0, kk, s0a + kk, 2) STEP_B(0, kk, s0a + kk, 2) }
        ADV()
        #pragma unroll
        for (int kk = 0; kk < 8; kk++) { STEP_A(8, kk, s0a + 8 + kk, 2) STEP_B(8, kk, s0a + 8 + kk, 2) }
        ADV()
    }

#undef STEP_A
#undef STEP_B
#undef HSHIFT
#undef PRE_B
#undef ADV
#undef ROT

    if (q == 15 && lane == 31) g_R[prob] = rB;   // R[1023][1023]
}

// ---------------- kernel 4: combine into MSE loss --------------------------------
__global__ void combine_kernel(const float* __restrict__ labels, float* __restrict__ out) {
    const int b = threadIdx.x;
    float v = 0.0f;
    if (b < 8) {
        float sTX = g_R[0 * 8 + b];
        float sTT = g_R[1 * 8 + b];
        float sOX = g_R[2 * 8 + b];
        float sOO = g_R[3 * 8 + b];
        float diff = ((sTX - sOX) - 0.5f * (sTT - sOO)) * LN2 - labels[0];
        v = diff * diff;
    }
    #pragma unroll
    for (int o = 4; o > 0; o >>= 1) v += __shfl_down_sync(0xffffffffu, v, o);
    if (b == 0) out[0] = v * 0.125f;
}

// ---------------- launcher -------------------------------------------------------
extern "C" void kernel_launch(void* const* d_in, const int* in_sizes, int n_in,
                              void* d_out, int out_size) {
    const float* TGT    = (const float*)d_in[0];
    const float* OTH    = (const float*)d_in[1];
    const float* X      = (const float*)d_in[2];
    const float* labels = (const float*)d_in[3];
    float* out = (float*)d_out;

    init_kernel<<<1024, 512>>>();
    norm_kernel<<<dim3(1024, 3), 256>>>(TGT, OTH, X);
    cost_kernel<<<dim3(16, 16, 32), 64>>>();
    dp_kernel<<<128, 128>>>();
    combine_kernel<<<1, 32>>>(labels, out);
}

// round 13
// speedup vs baseline: 1.0450x; 1.0450x over previous
#include <cuda_runtime.h>
#include <cuda_bf16.h>
#include <math.h>

#define INF_F 1e10f
#define L2E   1.4426950408889634f
#define LN2   0.6931471805599453f
#define NDIAG 2072ull
#define SENT_U 0x7FC00000u

// ---------------- scratch (device globals) -------------------------------------
__device__ float g_norm[3u * 8192u * 64u];               // normalized rows
__device__ float g_cost[32ull * NDIAG * 1024ull];        // diag-major cost*L2E, PAD=8 lead
__device__ float g_hrow[32][1024];                       // ONE global halo per problem
__device__ float g_R[32];                                // DTW results (log2-scaled)

__device__ __forceinline__ float fexp2(float x) {
    float y; asm("ex2.approx.f32 %0, %1;" : "=f"(y) : "f"(x)); return y;
}
__device__ __forceinline__ float flog2(float x) {
    float y; asm("lg2.approx.f32 %0, %1;" : "=f"(y) : "f"(x)); return y;
}
__device__ __forceinline__ float ld_rlx(const float* p) {
    float v; asm volatile("ld.relaxed.gpu.global.f32 %0, [%1];" : "=f"(v) : "l"(p)); return v;
}
__device__ __forceinline__ void st_rlx(float* p, float v) {
    asm volatile("st.relaxed.gpu.global.f32 [%0], %1;" :: "l"(p), "f"(v) : "memory");
}
typedef unsigned long long u64;
__device__ __forceinline__ u64 ffma2(u64 a, u64 b, u64 c) {
    u64 d; asm("fma.rn.f32x2 %0, %1, %2, %3;" : "=l"(d) : "l"(a), "l"(b), "l"(c)); return d;
}
__device__ __forceinline__ u64 pack2(float x) {
    u64 d; asm("mov.b64 %0, {%1, %1};" : "=l"(d) : "f"(x)); return d;
}

// ---------------- kernel 0: fill global halo buffer with sentinel ----------------
__global__ void init_kernel() {
    unsigned t = blockIdx.x * 512u + threadIdx.x;        // 32768 words
    ((unsigned*)g_hrow)[t] = SENT_U;
}

// ---------------- kernel 1: row-wise L2 normalize -------------------------------
__global__ void norm_kernel(const float* __restrict__ A,
                            const float* __restrict__ B,
                            const float* __restrict__ C) {
    const int sel  = blockIdx.y;
    const int lane = threadIdx.x & 31;
    const int row  = blockIdx.x * 8 + (threadIdx.x >> 5);
    const float* src = (sel == 0) ? A : ((sel == 1) ? B : C);

    float2 v = *(const float2*)(src + (size_t)row * 64 + lane * 2);
    float ss = v.x * v.x + v.y * v.y;
    #pragma unroll
    for (int o = 16; o > 0; o >>= 1) ss += __shfl_xor_sync(0xffffffffu, ss, o);
    float scale = 1.0f / fmaxf(sqrtf(ss), 1e-8f);
    float* dst = g_norm + (size_t)sel * (8192u * 64u) + (size_t)row * 64 + lane * 2;
    *(float2*)dst = make_float2(v.x * scale, v.y * scale);
}

// ---------------- kernel 2: cost = L2E*(1 - dot), DIAGONAL-major (PAD=8) --------
__global__ void __launch_bounds__(64) cost_kernel() {
    const int pb   = blockIdx.z;
    const int p    = pb >> 3;
    const int bat  = pb & 7;
    const int asel = p >> 1;                 // TGT(0)/OTH(1)
    const int bsel = (p & 1) ? asel : 2;     // self or X(2)

    const float* Abase = g_norm + ((size_t)asel * 8192u + (size_t)bat * 1024u) * 64u;
    const float* Bbase = g_norm + ((size_t)bsel * 8192u + (size_t)bat * 1024u) * 64u;
    const int i0 = blockIdx.x * 64;
    const int j0 = blockIdx.y * 64;

    __shared__ float sAT[64 * 64];
    __shared__ float sBT[64 * 64];
    const int tid = threadIdx.x;

    {
        const float4* ap = (const float4*)(Abase + (size_t)(i0 + tid) * 64);
        const float4* bp = (const float4*)(Bbase + (size_t)(j0 + tid) * 64);
        #pragma unroll
        for (int q = 0; q < 16; q++) {
            float4 va = ap[q];
            sAT[(4 * q + 0) * 64 + tid] = va.x;
            sAT[(4 * q + 1) * 64 + tid] = va.y;
            sAT[(4 * q + 2) * 64 + tid] = va.z;
            sAT[(4 * q + 3) * 64 + tid] = va.w;
            float4 vb = bp[q];
            sBT[(4 * q + 0) * 64 + tid] = vb.x;
            sBT[(4 * q + 1) * 64 + tid] = vb.y;
            sBT[(4 * q + 2) * 64 + tid] = vb.z;
            sBT[(4 * q + 3) * 64 + tid] = vb.w;
        }
    }
    __syncthreads();

    const int ti = tid >> 3;
    const int tj = tid & 7;

    u64 acc[8][4];
    #pragma unroll
    for (int r = 0; r < 8; r++)
        #pragma unroll
        for (int c = 0; c < 4; c++) acc[r][c] = 0ull;

    #pragma unroll
    for (int k = 0; k < 64; k++) {
        float4 t0 = *(const float4*)&sAT[k * 64 + ti * 8];
        float4 t1 = *(const float4*)&sAT[k * 64 + ti * 8 + 4];
        u64 a2[8];
        a2[0] = pack2(t0.x); a2[1] = pack2(t0.y); a2[2] = pack2(t0.z); a2[3] = pack2(t0.w);
        a2[4] = pack2(t1.x); a2[5] = pack2(t1.y); a2[6] = pack2(t1.z); a2[7] = pack2(t1.w);
        ulonglong2 u0 = *(const ulonglong2*)&sBT[k * 64 + tj * 8];
        ulonglong2 u1 = *(const ulonglong2*)&sBT[k * 64 + tj * 8 + 4];
        u64 b2[4] = {u0.x, u0.y, u1.x, u1.y};
        #pragma unroll
        for (int r = 0; r < 8; r++)
            #pragma unroll
            for (int c = 0; c < 4; c++)
                acc[r][c] = ffma2(a2[r], b2[c], acc[r][c]);
    }
    __syncthreads();

    float* Cs = sAT;   // restage (alias) with affine transform applied
    #pragma unroll
    for (int r = 0; r < 8; r++) {
        float v[8];
        #pragma unroll
        for (int c = 0; c < 4; c++) {
            float lo, hi;
            asm("mov.b64 {%0, %1}, %2;" : "=f"(lo), "=f"(hi) : "l"(acc[r][c]));
            v[2 * c]     = fmaf(lo, -L2E, L2E);
            v[2 * c + 1] = fmaf(hi, -L2E, L2E);
        }
        *(float4*)&Cs[(ti * 8 + r) * 64 + tj * 8]     = make_float4(v[0], v[1], v[2], v[3]);
        *(float4*)&Cs[(ti * 8 + r) * 64 + tj * 8 + 4] = make_float4(v[4], v[5], v[6], v[7]);
    }
    __syncthreads();

    float* out = g_cost + (size_t)pb * (NDIAG * 1024ull);
    const int kbase = i0 + j0 + 8;            // PAD=8 leading diagonals
    for (int d = 0; d < 127; d++) {
        int lo = d - 63; if (lo < 0) lo = 0;
        int hi = d;      if (hi > 63) hi = 63;
        int i = lo + tid;
        if (i <= hi)
            out[(size_t)(kbase + d) * 1024u + (i0 + i)] = Cs[i * 64 + (d - i)];
    }
}

// ---------------- kernel 3: soft-DTW, in-CTA smem halo pipeline ------------------
// CTA (64 total) = 16 warps = strips ti = 16*half .. +15 of problem blockIdx.x>>1.
// In-CTA handoff: 512-col smem ring + volatile counters (miss cost ~60 cyc).
// Cross-CTA hop (1 per problem): global sentinel protocol (R8).
__global__ void __launch_bounds__(512) dp_kernel() {
    __shared__ float halo_s[15][512];
    __shared__ volatile int s_prod[16];   // producer col count per warp w (ring w)
    __shared__ volatile int s_cons[16];   // consumer progress per warp w

    const int w    = threadIdx.x >> 5;
    const int lane = threadIdx.x & 31;
    const int prob = blockIdx.x >> 1;
    const int half = blockIdx.x & 1;
    const int ti   = half * 16 + w;
    const int lid8 = lane & 7;

    if (threadIdx.x < 16) { s_prod[threadIdx.x] = 0; s_cons[threadIdx.x] = 0; }
    __syncthreads();

    const bool in_smem  = (w > 0);
    const bool in_glob  = (w == 0 && half == 1);
    const bool out_smem = (w < 15);
    const bool out_glob = (w == 15 && half == 0);

    const float* cbase = g_cost + ((size_t)prob * NDIAG + (unsigned)(32 * ti + 8)) * 1024ull
                       + 32 * ti + lane;
    const float* ghin     = &g_hrow[prob][0];
    float*       ghout    = &g_hrow[prob][0];
    const float* ring_in  = in_smem  ? &halo_s[w - 1][0] : &halo_s[0][0];
    float*       ring_out = out_smem ? &halo_s[w][0]     : &halo_s[0][0];

    // 16-deep cost register pipe
    float c[16];
    #pragma unroll
    for (int k = 0; k < 16; k++) c[k] = __ldg(cbase + (size_t)k * 1024u);

    float rA  = INF_F, upA = INF_F;
    float dgA = (ti == 0 && lane == 0) ? 0.0f : INF_F;

    // halo input state
    float hv0 = INF_F, hv1 = 0.0f, hv2 = 0.0f;
    if (in_smem) {
        while (s_prod[w - 1] < 8) __nanosleep(32);
        __threadfence_block();
        hv0 = ring_in[lid8];
    } else if (in_glob) {
        hv0 = ld_rlx(ghin + lid8);
        while (__any_sync(0xffffffffu, __float_as_uint(hv0) == SENT_U)) {
            __nanosleep(128);
            hv0 = ld_rlx(ghin + lid8);
        }
        hv1 = ld_rlx(ghin + 8 + lid8);
        hv2 = ld_rlx(ghin + 16 + lid8);
    }

    const float* cpf = cbase + 16 * 1024;    // prefetch pointer
    int col = -31;                            // lane31 store col at KK=0 of this group

#define DTW_STEP(SLOT0, KK, MODE)                                              \
    {                                                                          \
        float Dv = c[(SLOT0) + (KK)];                                          \
        c[(SLOT0) + (KK)] = __ldg(cpf + (KK) * 1024);                          \
        float topv = __shfl_sync(0xffffffffu, hv0, (KK));                      \
        float u = (lane == 0) ? topv : upA;                                    \
        float p   = fminf(u, dgA);                                             \
        float qq  = fmaxf(u, dgA);                                             \
        float mn  = fminf(p, rA);                                              \
        float mx  = fmaxf(qq, rA);                                             \
        float mid = fmaxf(p, fminf(qq, rA));                                   \
        float curv = (Dv + mn) - flog2((1.0f + fexp2(mn - mid)) + fexp2(mn - mx)); \
        int cc = col + (KK);                                                   \
        bool act = (MODE == 0) ? true                                          \
                 : ((MODE == 1) ? (cc + 31 >= lane)                            \
                                : (cc + 31 - lane <= 1023));                   \
        float ncur = act ? curv : rA;                                          \
        bool st31 = act && (lane == 31);                                       \
        if (st31 && out_smem) ring_out[cc & 511] = ncur;                       \
        if (st31 && out_glob) st_rlx(ghout + cc, ncur);                        \
        dgA = u;                                                               \
        rA  = ncur;                                                            \
        upA = __shfl_up_sync(0xffffffffu, rA, 1);                              \
    }

#define ROT_IN(G)                                                              \
    if ((G) <= 126) {                                                          \
        if (in_smem) {                                                         \
            int need = 8 * (G) + 16;                                           \
            while (s_prod[w - 1] < need) __nanosleep(32);                      \
            __threadfence_block();                                             \
            hv0 = ring_in[(8 * (G) + 8 + lid8) & 511];                         \
            if (lane == 0) s_cons[w] = need;                                   \
        } else if (in_glob) {                                                  \
            while (__any_sync(0xffffffffu, __float_as_uint(hv1) == SENT_U))    \
                hv1 = ld_rlx(ghin + 8 * ((G) + 1) + lid8);                     \
            hv0 = hv1; hv1 = hv2;                                              \
            int a = 8 * ((G) + 3); if (a > 1016) a = 1016;                     \
            hv2 = ld_rlx(ghin + a + lid8);                                     \
        }                                                                      \
    }

#define ROT_OUT(G)                                                             \
    if (out_smem) {                                                            \
        int limit = 8 * (G) - 527;                                             \
        if (limit > 0) { while (s_cons[w + 1] < limit) __nanosleep(64); }      \
        int cnt = 8 * (G) - 23;                                                \
        if (cnt > 1024) cnt = 1024;                                            \
        if (cnt > 0 && lane == 31) { __threadfence_block(); s_prod[w] = cnt; } \
    }

#define ADV() { cpf += 8 * 1024; col += 8; }

    // ---- prologue: groups 0..3 (s = 0..31), masked ----
    #pragma unroll
    for (int kk = 0; kk < 8; kk++) DTW_STEP(0, kk, 1)
    ROT_IN(0) ROT_OUT(0) ADV()
    #pragma unroll
    for (int kk = 0; kk < 8; kk++) DTW_STEP(8, kk, 1)
    ROT_IN(1) ROT_OUT(1) ADV()
    #pragma unroll
    for (int kk = 0; kk < 8; kk++) DTW_STEP(0, kk, 1)
    ROT_IN(2) ROT_OUT(2) ADV()
    #pragma unroll
    for (int kk = 0; kk < 8; kk++) DTW_STEP(8, kk, 1)
    ROT_IN(3) ROT_OUT(3) ADV()

    // ---- steady region: groups 4..127 (s = 32..1023), all lanes active ----
    for (int g = 4; g < 128; g += 2) {
        #pragma unroll
        for (int kk = 0; kk < 8; kk++) DTW_STEP(0, kk, 0)
        ROT_IN(g) ROT_OUT(g) ADV()
        #pragma unroll
        for (int kk = 0; kk < 8; kk++) DTW_STEP(8, kk, 0)
        ROT_IN(g + 1) ROT_OUT(g + 1) ADV()
    }

    // ---- epilogue: groups 128..131 (s = 1024..1055), masked, publish only ----
    #pragma unroll
    for (int kk = 0; kk < 8; kk++) DTW_STEP(0, kk, 2)
    ROT_OUT(128) ADV()
    #pragma unroll
    for (int kk = 0; kk < 8; kk++) DTW_STEP(8, kk, 2)
    ROT_OUT(129) ADV()
    #pragma unroll
    for (int kk = 0; kk < 8; kk++) DTW_STEP(0, kk, 2)
    ROT_OUT(130) ADV()
    #pragma unroll
    for (int kk = 0; kk < 8; kk++) DTW_STEP(8, kk, 2)
    ROT_OUT(131) ADV()

#undef DTW_STEP
#undef ROT_IN
#undef ROT_OUT
#undef ADV

    if (ti == 31 && lane == 31) g_R[prob] = rA;   // R[1023][1023]
}

// ---------------- kernel 4: combine into MSE loss --------------------------------
__global__ void combine_kernel(const float* __restrict__ labels, float* __restrict__ out) {
    const int b = threadIdx.x;
    float v = 0.0f;
    if (b < 8) {
        float sTX = g_R[0 * 8 + b];
        float sTT = g_R[1 * 8 + b];
        float sOX = g_R[2 * 8 + b];
        float sOO = g_R[3 * 8 + b];
        float diff = ((sTX - sOX) - 0.5f * (sTT - sOO)) * LN2 - labels[0];
        v = diff * diff;
    }
    #pragma unroll
    for (int o = 4; o > 0; o >>= 1) v += __shfl_down_sync(0xffffffffu, v, o);
    if (b == 0) out[0] = v * 0.125f;
}

// ---------------- launcher -------------------------------------------------------
extern "C" void kernel_launch(void* const* d_in, const int* in_sizes, int n_in,
                              void* d_out, int out_size) {
    const float* TGT    = (const float*)d_in[0];
    const float* OTH    = (const float*)d_in[1];
    const float* X      = (const float*)d_in[2];
    const float* labels = (const float*)d_in[3];
    float* out = (float*)d_out;

    init_kernel<<<64, 512>>>();
    norm_kernel<<<dim3(1024, 3), 256>>>(TGT, OTH, X);
    cost_kernel<<<dim3(16, 16, 32), 64>>>();
    dp_kernel<<<64, 512>>>();
    combine_kernel<<<1, 32>>>(labels, out);
}